// round 15
// baseline (speedup 1.0000x reference)
#include <cuda_runtime.h>
#include <cuda_bf16.h>
#include <cuda_fp16.h>
#include <stdint.h>
#include <math.h>

// Problem constants (fixed): B=2, S=2048, D=2048, H=16
#define BATCH  2
#define SEQ    2048
#define DMODEL 2048
#define NHEAD  16
#define HDIM   128
#define MROWS  (BATCH * SEQ)   // 4096

// ================= scratch (device globals: allocation-free) =================
__device__ __half g_xh [(size_t)MROWS * DMODEL];
__device__ __half g_qh [(size_t)MROWS * DMODEL];
__device__ __half g_kh [(size_t)MROWS * DMODEL];
__device__ __half g_vh [(size_t)MROWS * DMODEL];
__device__ __half g_aoh[(size_t)MROWS * DMODEL];

__device__ __half g_wqh[(size_t)DMODEL * DMODEL];
__device__ __half g_wkh[(size_t)DMODEL * DMODEL];
__device__ __half g_wvh[(size_t)DMODEL * DMODEL];
__device__ __half g_wph[(size_t)DMODEL * DMODEL];

// ================= PTX helpers (baseline features only) ======
__device__ __forceinline__ uint32_t smem_u32(const void* p) {
    uint32_t a;
    asm("{ .reg .u64 t; cvta.to.shared.u64 t, %1; cvt.u32.u64 %0, t; }" : "=r"(a) : "l"(p));
    return a;
}
__device__ __forceinline__ void cp_async16(uint32_t dst, const void* src) {
    asm volatile("cp.async.cg.shared.global [%0], [%1], 16;" :: "r"(dst), "l"(src) : "memory");
}
__device__ __forceinline__ void cp_commit() {
    asm volatile("cp.async.commit_group;" ::: "memory");
}
__device__ __forceinline__ void cp_wait2() {
    asm volatile("cp.async.wait_group 2;" ::: "memory");
}
__device__ __forceinline__ void cp_wait1() {
    asm volatile("cp.async.wait_group 1;" ::: "memory");
}
__device__ __forceinline__ void cp_wait0() {
    asm volatile("cp.async.wait_group 0;" ::: "memory");
}
__device__ __forceinline__ void ldm_x4(uint32_t& r0, uint32_t& r1, uint32_t& r2, uint32_t& r3,
                                       uint32_t addr) {
    asm volatile("ldmatrix.sync.aligned.m8n8.x4.shared.b16 {%0,%1,%2,%3}, [%4];"
                 : "=r"(r0), "=r"(r1), "=r"(r2), "=r"(r3) : "r"(addr));
}
__device__ __forceinline__ void ldm_x4_t(uint32_t& r0, uint32_t& r1, uint32_t& r2, uint32_t& r3,
                                         uint32_t addr) {
    asm volatile("ldmatrix.sync.aligned.m8n8.x4.trans.shared.b16 {%0,%1,%2,%3}, [%4];"
                 : "=r"(r0), "=r"(r1), "=r"(r2), "=r"(r3) : "r"(addr));
}
__device__ __forceinline__ void mma_f16(float* c, const uint32_t* a, uint32_t b0, uint32_t b1) {
    asm volatile("mma.sync.aligned.m16n8k16.row.col.f32.f16.f16.f32 "
                 "{%0,%1,%2,%3}, {%4,%5,%6,%7}, {%8,%9}, {%0,%1,%2,%3};"
                 : "+f"(c[0]), "+f"(c[1]), "+f"(c[2]), "+f"(c[3])
                 : "r"(a[0]), "r"(a[1]), "r"(a[2]), "r"(a[3]), "r"(b0), "r"(b1));
}
__device__ __forceinline__ uint32_t pack_f16x2(float f0, float f1) {
    uint32_t r;
    asm("cvt.rn.f16x2.f32 %0, %1, %2;" : "=r"(r) : "f"(f1), "f"(f0));
    return r;
}

// ================= conversion kernel =================
struct CvtSet {
    const float* src[4];
    __half* dst[4];
};
__global__ __launch_bounds__(256) void cvt4_f16_kernel(CvtSet s, int n4)
{
    int i = blockIdx.x * blockDim.x + threadIdx.x;
    if (i >= n4) return;
    int t = blockIdx.y;
    float4 v = ((const float4*)s.src[t])[i];
    uint2 o;
    o.x = pack_f16x2(v.x, v.y);
    o.y = pack_f16x2(v.z, v.w);
    ((uint2*)s.dst[t])[i] = o;
}

// ================= fp16 GEMM: C[M,N] = A[M,K] @ B[N,K]^T =====================
// Single-term fp16. CTA tile 128x128, BK=64, 256 threads, 3-stage cp.async.
#define GBK     64
#define TILE_B  (128 * 128)                  // 16 KB per tile

#define T_A  0
#define T_B  (1 * TILE_B)

#define GEMM_STAGE_B (2 * TILE_B)            // 32 KB per stage
#define GEMM_SMEM    (3 * GEMM_STAGE_B)      // 98304 (3 stages)

// MODE 0: fp32 out. MODE 2: fp16 out scaled by mul.
template<int MODE>
__device__ __forceinline__ void gemm_tile_body(
    const __half* __restrict__ A, const __half* __restrict__ B,
    float* __restrict__ C, __half* __restrict__ Ch, float mul, int M, int N, int K,
    int m0, int n0, char* smem)
{
    const uint32_t sb = smem_u32(smem);
    const int tid = threadIdx.x;
    const int wid = tid >> 5;
    const int l   = tid & 31;
    const int wm  = wid & 3;
    const int wn  = wid >> 2;

    int lrow[4], ldst[4];
    #pragma unroll
    for (int i = 0; i < 4; i++) {
        int idx = tid + i * 256;
        int row = idx >> 3, c16 = idx & 7;
        lrow[i] = row;
        ldst[i] = row * 128 + ((c16 ^ (row & 7)) << 4);
    }

    auto issue_stage = [&](int c, int buf) {
        uint32_t s0 = sb + buf * GEMM_STAGE_B;
        #pragma unroll
        for (int i = 0; i < 4; i++) {
            int row = lrow[i];
            int koff = c * GBK + ((tid + i * 256) & 7) * 8;
            cp_async16(s0 + T_A + ldst[i], A + (size_t)(m0 + row) * K + koff);
            cp_async16(s0 + T_B + ldst[i], B + (size_t)(n0 + row) * K + koff);
        }
        cp_commit();
    };

    const int a_rowoff = (l & 15);
    const int a_c16off = (l >> 4);
    const int b_rowoff = (l & 7) | ((l & 16) >> 1);
    const int b_c16off = (l >> 3) & 1;

    float acc[2][8][4];
    #pragma unroll
    for (int mi = 0; mi < 2; mi++)
        #pragma unroll
        for (int nj = 0; nj < 8; nj++)
            #pragma unroll
            for (int t = 0; t < 4; t++) acc[mi][nj][t] = 0.f;

    const int nchunks = K / GBK;        // 32
    issue_stage(0, 0);
    issue_stage(1, 1);
    issue_stage(2, 2);

    for (int c = 0; c < nchunks; c++) {
        const int buf = c % 3;
        if (c <= nchunks - 3)      cp_wait2();
        else if (c == nchunks - 2) cp_wait1();
        else                       cp_wait0();
        __syncthreads();

        const uint32_t s0 = sb + buf * GEMM_STAGE_B;
        #pragma unroll
        for (int kk = 0; kk < 4; kk++) {
            uint32_t a[2][4];
            #pragma unroll
            for (int mi = 0; mi < 2; mi++) {
                int row = wm * 32 + mi * 16 + a_rowoff;
                int c16 = kk * 2 + a_c16off;
                uint32_t ad = s0 + T_A + row * 128 + ((c16 ^ (row & 7)) << 4);
                ldm_x4(a[mi][0], a[mi][1], a[mi][2], a[mi][3], ad);
            }
            uint32_t bh[8][2];
            #pragma unroll
            for (int p = 0; p < 4; p++) {
                int row = wn * 64 + p * 16 + b_rowoff;
                int c16 = kk * 2 + b_c16off;
                uint32_t ad = s0 + T_B + row * 128 + ((c16 ^ (row & 7)) << 4);
                ldm_x4(bh[2*p][0], bh[2*p][1], bh[2*p+1][0], bh[2*p+1][1], ad);
            }
            #pragma unroll
            for (int mi = 0; mi < 2; mi++)
                #pragma unroll
                for (int nj = 0; nj < 8; nj++)
                    mma_f16(acc[mi][nj], a[mi], bh[nj][0], bh[nj][1]);
        }
        __syncthreads();
        if (c + 3 < nchunks) issue_stage(c + 3, buf);
    }

    const int er = l >> 2;
    const int ec = (l & 3) * 2;
    #pragma unroll
    for (int mi = 0; mi < 2; mi++) {
        int grow = m0 + wm * 32 + mi * 16 + er;
        #pragma unroll
        for (int nj = 0; nj < 8; nj++) {
            int gcol = n0 + wn * 64 + nj * 8 + ec;
            if (MODE == 0) {
                *(float2*)&C[(size_t)grow * N + gcol] =
                    make_float2(acc[mi][nj][0], acc[mi][nj][1]);
                *(float2*)&C[(size_t)(grow + 8) * N + gcol] =
                    make_float2(acc[mi][nj][2], acc[mi][nj][3]);
            } else {
                *(uint32_t*)&Ch[(size_t)grow * N + gcol] =
                    pack_f16x2(acc[mi][nj][0] * mul, acc[mi][nj][1] * mul);
                *(uint32_t*)&Ch[(size_t)(grow + 8) * N + gcol] =
                    pack_f16x2(acc[mi][nj][2] * mul, acc[mi][nj][3] * mul);
            }
        }
    }
}

// projection: 1-term, fp32 out
__global__ __launch_bounds__(256) void gemm_f32out_kernel(
    const __half* __restrict__ A, const __half* __restrict__ B,
    float* __restrict__ C, int M, int N, int K)
{
    extern __shared__ char smem[];
    gemm_tile_body<0>(A, B, C, nullptr, 1.0f,
                      M, N, K, blockIdx.y * 128, blockIdx.x * 128, smem);
}

// fused QKV: 1-term, fp16 out
struct QKVSet {
    const __half* b[3];
    __half* ch[3];
    float mul[3];
};
__global__ __launch_bounds__(256) void gemm_qkv_kernel(
    const __half* __restrict__ A, QKVSet s, int M, int N, int K)
{
    extern __shared__ char smem[];
    const int z = blockIdx.z;
    gemm_tile_body<2>(A, s.b[z], nullptr, s.ch[z],
                      s.mul[z], M, N, K, blockIdx.y * 128, blockIdx.x * 128, smem);
}

// ============================================================
// Tensor-core flash attention v3 (causal) — fp16.
// Block: 256 threads (8 warps); BQ=128, BKV=64, hd=128.
// Plain __launch_bounds__(256): natural regs (~170), no spills (round-11 cfg).
// smem: Q 32KB + 2 stages x 32KB = 96 KB.
// ============================================================
#define FT_Q     0
#define FT_STAGE 32768
#define FS_K     0
#define FS_V     16384
#define FLASH_TC_SMEM 98304

__device__ __forceinline__ uint32_t fsw(int row, int c16) {
    return (uint32_t)(row * 256 + ((c16 ^ ((row & 7) << 1)) << 4));
}

__global__ __launch_bounds__(256) void flash_attn_tc_kernel(
    const __half* __restrict__ qh, const __half* __restrict__ kh,
    const __half* __restrict__ vh, __half* __restrict__ oh)
{
    extern __shared__ char fsm[];
    const uint32_t sb = smem_u32(fsm);
    const int tid = threadIdx.x;
    const int wid = tid >> 5;
    const int l   = tid & 31;
    const int qt = gridDim.x - 1 - blockIdx.x;   // longest-first scheduling
    const int h  = blockIdx.y;
    const int b  = blockIdx.z;
    const int q0 = qt * 128;

    const size_t gq = ((size_t)b * SEQ + q0) * DMODEL + h * HDIM;
    #pragma unroll
    for (int i = 0; i < 8; i++) {
        int idx = tid + i * 256;
        int row = idx >> 4, c16 = idx & 15;
        cp_async16(sb + FT_Q + fsw(row, c16), qh + gq + (size_t)row * DMODEL + c16 * 8);
    }
    cp_commit();

    auto issue_kv = [&](int kt, int sidx) {
        uint32_t s0 = sb + FT_STAGE + sidx * 32768;
        const size_t gkv = ((size_t)b * SEQ + kt * 64) * DMODEL + h * HDIM;
        #pragma unroll
        for (int i = 0; i < 4; i++) {
            int idx = tid + i * 256;
            int row = idx >> 4, c16 = idx & 15;
            uint32_t off = fsw(row, c16);
            size_t src = gkv + (size_t)row * DMODEL + c16 * 8;
            cp_async16(s0 + FS_K + off, kh + src);
            cp_async16(s0 + FS_V + off, vh + src);
        }
        cp_commit();
    };

    const int r  = l >> 2;
    const int cq = l & 3;
    const int a_rowoff = (l & 15);
    const int a_c16off = (l >> 4);
    const int b_rowoff = (l & 7) | ((l & 16) >> 1);
    const int b_c16off = (l >> 3) & 1;
    const int wrow0 = q0 + wid * 16;

    float m0v = -1e30f, m1v = -1e30f, l0v = 0.f, l1v = 0.f;
    float O[16][4];
    #pragma unroll
    for (int g = 0; g < 16; g++)
        #pragma unroll
        for (int t = 0; t < 4; t++) O[g][t] = 0.f;

    const int nkt = 2 * qt + 2;
    issue_kv(0, 0);

    for (int kt = 0; kt < nkt; kt++) {
        const int sidx = kt & 1;
        if (kt + 1 < nkt) issue_kv(kt + 1, sidx ^ 1);
        if (kt + 1 < nkt) cp_wait1(); else cp_wait0();
        __syncthreads();

        const int col0 = kt * 64;
        if (col0 <= wrow0 + 15) {        // warp-level causal skip
            const uint32_t s0 = sb + FT_STAGE + sidx * 32768;

            float s[8][4];
            #pragma unroll
            for (int nj = 0; nj < 8; nj++)
                #pragma unroll
                for (int t = 0; t < 4; t++) s[nj][t] = 0.f;

            #pragma unroll
            for (int j = 0; j < 8; j++) {
                int arow = wid * 16 + a_rowoff;
                uint32_t ah[4];
                ldm_x4(ah[0], ah[1], ah[2], ah[3], sb + FT_Q + fsw(arow, 2 * j + a_c16off));

                uint32_t bh[8][2];
                #pragma unroll
                for (int p = 0; p < 4; p++) {
                    int brow = p * 16 + b_rowoff;
                    uint32_t bad = s0 + FS_K + fsw(brow, 2 * j + b_c16off);
                    ldm_x4(bh[2*p][0], bh[2*p][1], bh[2*p+1][0], bh[2*p+1][1], bad);
                }
                #pragma unroll
                for (int nj = 0; nj < 8; nj++)
                    mma_f16(s[nj], ah, bh[nj][0], bh[nj][1]);
            }

            if (col0 + 63 > wrow0) {
                #pragma unroll
                for (int nj = 0; nj < 8; nj++)
                    #pragma unroll
                    for (int t = 0; t < 4; t++) {
                        int coll = col0 + nj * 8 + 2 * cq + (t & 1);
                        int rowl = wrow0 + r + ((t >> 1) << 3);
                        if (coll > rowl) s[nj][t] = -1e30f;
                    }
            }

            float mx0 = -1e30f, mx1 = -1e30f;
            #pragma unroll
            for (int nj = 0; nj < 8; nj++) {
                mx0 = fmaxf(mx0, fmaxf(s[nj][0], s[nj][1]));
                mx1 = fmaxf(mx1, fmaxf(s[nj][2], s[nj][3]));
            }
            mx0 = fmaxf(mx0, __shfl_xor_sync(0xffffffffu, mx0, 1));
            mx0 = fmaxf(mx0, __shfl_xor_sync(0xffffffffu, mx0, 2));
            mx1 = fmaxf(mx1, __shfl_xor_sync(0xffffffffu, mx1, 1));
            mx1 = fmaxf(mx1, __shfl_xor_sync(0xffffffffu, mx1, 2));

            float mn0 = fmaxf(m0v, mx0), mn1 = fmaxf(m1v, mx1);
            float al0 = __expf(m0v - mn0), al1 = __expf(m1v - mn1);
            m0v = mn0; m1v = mn1;

            #pragma unroll
            for (int g = 0; g < 16; g++) {
                O[g][0] *= al0; O[g][1] *= al0;
                O[g][2] *= al1; O[g][3] *= al1;
            }

            float rs0 = 0.f, rs1 = 0.f;
            #pragma unroll
            for (int nj = 0; nj < 8; nj++) {
                s[nj][0] = __expf(s[nj][0] - mn0);
                s[nj][1] = __expf(s[nj][1] - mn0);
                s[nj][2] = __expf(s[nj][2] - mn1);
                s[nj][3] = __expf(s[nj][3] - mn1);
                rs0 += s[nj][0] + s[nj][1];
                rs1 += s[nj][2] + s[nj][3];
            }
            rs0 += __shfl_xor_sync(0xffffffffu, rs0, 1);
            rs0 += __shfl_xor_sync(0xffffffffu, rs0, 2);
            rs1 += __shfl_xor_sync(0xffffffffu, rs1, 1);
            rs1 += __shfl_xor_sync(0xffffffffu, rs1, 2);
            l0v = l0v * al0 + rs0;
            l1v = l1v * al1 + rs1;

            #pragma unroll
            for (int j = 0; j < 4; j++) {
                uint32_t pa[4];
                pa[0] = pack_f16x2(s[2*j][0],   s[2*j][1]);
                pa[1] = pack_f16x2(s[2*j][2],   s[2*j][3]);
                pa[2] = pack_f16x2(s[2*j+1][0], s[2*j+1][1]);
                pa[3] = pack_f16x2(s[2*j+1][2], s[2*j+1][3]);
                #pragma unroll
                for (int g = 0; g < 8; g++) {
                    int vrow = j * 16 + (l & 15);
                    uint32_t vad = s0 + FS_V + fsw(vrow, 2 * g + (l >> 4));
                    uint32_t v0, v1, v2, v3;
                    ldm_x4_t(v0, v1, v2, v3, vad);
                    mma_f16(O[2*g],     pa, v0, v1);
                    mma_f16(O[2*g + 1], pa, v2, v3);
                }
            }
        }
        __syncthreads();
    }

    const float i0 = 1.0f / l0v;
    const float i1 = 1.0f / l1v;
    const size_t obase = ((size_t)b * SEQ + q0 + wid * 16 + r) * DMODEL + h * HDIM;
    #pragma unroll
    for (int g = 0; g < 16; g++) {
        int col = g * 8 + 2 * cq;
        *(uint32_t*)&oh[obase + col] = pack_f16x2(O[g][0] * i0, O[g][1] * i0);
        *(uint32_t*)&oh[obase + (size_t)8 * DMODEL + col] =
            pack_f16x2(O[g][2] * i1, O[g][3] * i1);
    }
}

// ============================================================
// launcher
// ============================================================
extern "C" void kernel_launch(void* const* d_in, const int* in_sizes, int n_in,
                              void* d_out, int out_size)
{
    const float* x  = (const float*)d_in[0];
    const float* Wq = (const float*)d_in[1];
    const float* Wk = (const float*)d_in[2];
    const float* Wv = (const float*)d_in[3];
    const float* Wp = (const float*)d_in[4];
    float* out = (float*)d_out;

    void *xh, *qh, *kh, *vh, *aoh;
    cudaGetSymbolAddress(&xh,  g_xh);
    cudaGetSymbolAddress(&qh,  g_qh);
    cudaGetSymbolAddress(&kh,  g_kh);
    cudaGetSymbolAddress(&vh,  g_vh);
    cudaGetSymbolAddress(&aoh, g_aoh);

    void *wqh, *wkh, *wvh, *wph;
    cudaGetSymbolAddress(&wqh, g_wqh);
    cudaGetSymbolAddress(&wkh, g_wkh);
    cudaGetSymbolAddress(&wvh, g_wvh);
    cudaGetSymbolAddress(&wph, g_wph);

    cudaFuncSetAttribute(flash_attn_tc_kernel,
                         cudaFuncAttributeMaxDynamicSharedMemorySize, FLASH_TC_SMEM);
    cudaFuncSetAttribute(gemm_f32out_kernel,
                         cudaFuncAttributeMaxDynamicSharedMemorySize, GEMM_SMEM);
    cudaFuncSetAttribute(gemm_qkv_kernel,
                         cudaFuncAttributeMaxDynamicSharedMemorySize, GEMM_SMEM);

    const int nx4 = (MROWS * DMODEL) / 4;
    const int nw4 = (DMODEL * DMODEL) / 4;

    {
        CvtSet sx;
        sx.src[0] = x; sx.dst[0] = (__half*)xh;
        dim3 g1((nx4 + 255) / 256, 1);
        cvt4_f16_kernel<<<g1, 256>>>(sx, nx4);

        CvtSet sw;
        sw.src[0] = Wq; sw.dst[0] = (__half*)wqh;
        sw.src[1] = Wk; sw.dst[1] = (__half*)wkh;
        sw.src[2] = Wv; sw.dst[2] = (__half*)wvh;
        sw.src[3] = Wp; sw.dst[3] = (__half*)wph;
        dim3 g4((nw4 + 255) / 256, 4);
        cvt4_f16_kernel<<<g4, 256>>>(sw, nw4);
    }

    const float scale = 0.08838834764831845f;  // 1/sqrt(128), folded into Q

    {
        QKVSet qs;
        qs.b[0] = (const __half*)wqh; qs.ch[0] = (__half*)qh; qs.mul[0] = scale;
        qs.b[1] = (const __half*)wkh; qs.ch[1] = (__half*)kh; qs.mul[1] = 1.0f;
        qs.b[2] = (const __half*)wvh; qs.ch[2] = (__half*)vh; qs.mul[2] = 1.0f;
        dim3 qg(DMODEL / 128, MROWS / 128, 3);   // (16, 32, 3)
        gemm_qkv_kernel<<<qg, 256, GEMM_SMEM>>>(
            (const __half*)xh, qs, MROWS, DMODEL, DMODEL);
    }

    dim3 fgrid(SEQ / 128, NHEAD, BATCH);     // (16, 16, 2)
    flash_attn_tc_kernel<<<fgrid, 256, FLASH_TC_SMEM>>>(
        (const __half*)qh, (const __half*)kh, (const __half*)vh, (__half*)aoh);

    dim3 ggrid(DMODEL / 128, MROWS / 128);   // (16, 32)
    gemm_f32out_kernel<<<ggrid, 256, GEMM_SMEM>>>(
        (const __half*)aoh, (const __half*)wph,
        out, MROWS, DMODEL, DMODEL);
}

// round 16
// speedup vs baseline: 1.0214x; 1.0214x over previous
#include <cuda_runtime.h>
#include <cuda_bf16.h>
#include <cuda_fp16.h>
#include <stdint.h>
#include <math.h>

// Problem constants (fixed): B=2, S=2048, D=2048, H=16
#define BATCH  2
#define SEQ    2048
#define DMODEL 2048
#define NHEAD  16
#define HDIM   128
#define MROWS  (BATCH * SEQ)   // 4096

// ================= scratch (device globals: allocation-free) =================
__device__ __half g_xh [(size_t)MROWS * DMODEL];
__device__ __half g_qh [(size_t)MROWS * DMODEL];
__device__ __half g_kh [(size_t)MROWS * DMODEL];
__device__ __half g_vh [(size_t)MROWS * DMODEL];
__device__ __half g_aoh[(size_t)MROWS * DMODEL];

__device__ __half g_wqh[(size_t)DMODEL * DMODEL];
__device__ __half g_wkh[(size_t)DMODEL * DMODEL];
__device__ __half g_wvh[(size_t)DMODEL * DMODEL];
__device__ __half g_wph[(size_t)DMODEL * DMODEL];

// ================= PTX helpers (baseline features only) ======
__device__ __forceinline__ uint32_t smem_u32(const void* p) {
    uint32_t a;
    asm("{ .reg .u64 t; cvta.to.shared.u64 t, %1; cvt.u32.u64 %0, t; }" : "=r"(a) : "l"(p));
    return a;
}
__device__ __forceinline__ void cp_async16(uint32_t dst, const void* src) {
    asm volatile("cp.async.cg.shared.global [%0], [%1], 16;" :: "r"(dst), "l"(src) : "memory");
}
__device__ __forceinline__ void cp_commit() {
    asm volatile("cp.async.commit_group;" ::: "memory");
}
__device__ __forceinline__ void cp_wait1() {
    asm volatile("cp.async.wait_group 1;" ::: "memory");
}
__device__ __forceinline__ void cp_wait0() {
    asm volatile("cp.async.wait_group 0;" ::: "memory");
}
__device__ __forceinline__ void ldm_x4(uint32_t& r0, uint32_t& r1, uint32_t& r2, uint32_t& r3,
                                       uint32_t addr) {
    asm volatile("ldmatrix.sync.aligned.m8n8.x4.shared.b16 {%0,%1,%2,%3}, [%4];"
                 : "=r"(r0), "=r"(r1), "=r"(r2), "=r"(r3) : "r"(addr));
}
__device__ __forceinline__ void ldm_x4_t(uint32_t& r0, uint32_t& r1, uint32_t& r2, uint32_t& r3,
                                         uint32_t addr) {
    asm volatile("ldmatrix.sync.aligned.m8n8.x4.trans.shared.b16 {%0,%1,%2,%3}, [%4];"
                 : "=r"(r0), "=r"(r1), "=r"(r2), "=r"(r3) : "r"(addr));
}
__device__ __forceinline__ void mma_f16(float* c, const uint32_t* a, uint32_t b0, uint32_t b1) {
    asm volatile("mma.sync.aligned.m16n8k16.row.col.f32.f16.f16.f32 "
                 "{%0,%1,%2,%3}, {%4,%5,%6,%7}, {%8,%9}, {%0,%1,%2,%3};"
                 : "+f"(c[0]), "+f"(c[1]), "+f"(c[2]), "+f"(c[3])
                 : "r"(a[0]), "r"(a[1]), "r"(a[2]), "r"(a[3]), "r"(b0), "r"(b1));
}
__device__ __forceinline__ uint32_t pack_f16x2(float f0, float f1) {
    uint32_t r;
    asm("cvt.rn.f16x2.f32 %0, %1, %2;" : "=r"(r) : "f"(f1), "f"(f0));
    return r;
}

// ================= conversion kernel =================
struct CvtSet {
    const float* src[4];
    __half* dst[4];
};
__global__ __launch_bounds__(256) void cvt4_f16_kernel(CvtSet s, int n4)
{
    int i = blockIdx.x * blockDim.x + threadIdx.x;
    if (i >= n4) return;
    int t = blockIdx.y;
    float4 v = ((const float4*)s.src[t])[i];
    uint2 o;
    o.x = pack_f16x2(v.x, v.y);
    o.y = pack_f16x2(v.z, v.w);
    ((uint2*)s.dst[t])[i] = o;
}

// ================= fp16 GEMM: C[M,N] = A[M,K] @ B[N,K]^T =====================
// Single-term fp16. CTA tile 128x128, BK=64, 256 threads, 2-stage cp.async
// (64 KB smem -> 3 CTAs/SM; measured-best configuration).
#define GBK     64
#define TILE_B  (128 * 128)                  // 16 KB per tile

#define T_A  0
#define T_B  (1 * TILE_B)

#define GEMM_STAGE_B (2 * TILE_B)            // 32 KB per stage
#define GEMM_SMEM    (2 * GEMM_STAGE_B)      // 65536 (2 stages)

// MODE 0: fp32 out. MODE 2: fp16 out scaled by mul.
template<int MODE>
__device__ __forceinline__ void gemm_tile_body(
    const __half* __restrict__ A, const __half* __restrict__ B,
    float* __restrict__ C, __half* __restrict__ Ch, float mul, int M, int N, int K,
    int m0, int n0, char* smem)
{
    const uint32_t sb = smem_u32(smem);
    const int tid = threadIdx.x;
    const int wid = tid >> 5;
    const int l   = tid & 31;
    const int wm  = wid & 3;
    const int wn  = wid >> 2;

    int lrow[4], ldst[4];
    #pragma unroll
    for (int i = 0; i < 4; i++) {
        int idx = tid + i * 256;
        int row = idx >> 3, c16 = idx & 7;
        lrow[i] = row;
        ldst[i] = row * 128 + ((c16 ^ (row & 7)) << 4);
    }

    auto issue_stage = [&](int c, int buf) {
        uint32_t s0 = sb + buf * GEMM_STAGE_B;
        #pragma unroll
        for (int i = 0; i < 4; i++) {
            int row = lrow[i];
            int koff = c * GBK + ((tid + i * 256) & 7) * 8;
            cp_async16(s0 + T_A + ldst[i], A + (size_t)(m0 + row) * K + koff);
            cp_async16(s0 + T_B + ldst[i], B + (size_t)(n0 + row) * K + koff);
        }
        cp_commit();
    };

    const int a_rowoff = (l & 15);
    const int a_c16off = (l >> 4);
    const int b_rowoff = (l & 7) | ((l & 16) >> 1);
    const int b_c16off = (l >> 3) & 1;

    float acc[2][8][4];
    #pragma unroll
    for (int mi = 0; mi < 2; mi++)
        #pragma unroll
        for (int nj = 0; nj < 8; nj++)
            #pragma unroll
            for (int t = 0; t < 4; t++) acc[mi][nj][t] = 0.f;

    const int nchunks = K / GBK;        // 32
    issue_stage(0, 0);
    issue_stage(1, 1);

    for (int c = 0; c < nchunks; c++) {
        const int buf = c & 1;
        if (c < nchunks - 2) cp_wait1(); else cp_wait0();
        __syncthreads();

        const uint32_t s0 = sb + buf * GEMM_STAGE_B;
        #pragma unroll
        for (int kk = 0; kk < 4; kk++) {
            uint32_t a[2][4];
            #pragma unroll
            for (int mi = 0; mi < 2; mi++) {
                int row = wm * 32 + mi * 16 + a_rowoff;
                int c16 = kk * 2 + a_c16off;
                uint32_t ad = s0 + T_A + row * 128 + ((c16 ^ (row & 7)) << 4);
                ldm_x4(a[mi][0], a[mi][1], a[mi][2], a[mi][3], ad);
            }
            uint32_t bh[8][2];
            #pragma unroll
            for (int p = 0; p < 4; p++) {
                int row = wn * 64 + p * 16 + b_rowoff;
                int c16 = kk * 2 + b_c16off;
                uint32_t ad = s0 + T_B + row * 128 + ((c16 ^ (row & 7)) << 4);
                ldm_x4(bh[2*p][0], bh[2*p][1], bh[2*p+1][0], bh[2*p+1][1], ad);
            }
            #pragma unroll
            for (int mi = 0; mi < 2; mi++)
                #pragma unroll
                for (int nj = 0; nj < 8; nj++)
                    mma_f16(acc[mi][nj], a[mi], bh[nj][0], bh[nj][1]);
        }
        __syncthreads();
        if (c + 2 < nchunks) issue_stage(c + 2, buf);
    }

    const int er = l >> 2;
    const int ec = (l & 3) * 2;
    #pragma unroll
    for (int mi = 0; mi < 2; mi++) {
        int grow = m0 + wm * 32 + mi * 16 + er;
        #pragma unroll
        for (int nj = 0; nj < 8; nj++) {
            int gcol = n0 + wn * 64 + nj * 8 + ec;
            if (MODE == 0) {
                *(float2*)&C[(size_t)grow * N + gcol] =
                    make_float2(acc[mi][nj][0], acc[mi][nj][1]);
                *(float2*)&C[(size_t)(grow + 8) * N + gcol] =
                    make_float2(acc[mi][nj][2], acc[mi][nj][3]);
            } else {
                *(uint32_t*)&Ch[(size_t)grow * N + gcol] =
                    pack_f16x2(acc[mi][nj][0] * mul, acc[mi][nj][1] * mul);
                *(uint32_t*)&Ch[(size_t)(grow + 8) * N + gcol] =
                    pack_f16x2(acc[mi][nj][2] * mul, acc[mi][nj][3] * mul);
            }
        }
    }
}

// projection: 1-term, fp32 out
__global__ __launch_bounds__(256) void gemm_f32out_kernel(
    const __half* __restrict__ A, const __half* __restrict__ B,
    float* __restrict__ C, int M, int N, int K)
{
    extern __shared__ char smem[];
    gemm_tile_body<0>(A, B, C, nullptr, 1.0f,
                      M, N, K, blockIdx.y * 128, blockIdx.x * 128, smem);
}

// fused QKV: 1-term, fp16 out
struct QKVSet {
    const __half* b[3];
    __half* ch[3];
    float mul[3];
};
__global__ __launch_bounds__(256) void gemm_qkv_kernel(
    const __half* __restrict__ A, QKVSet s, int M, int N, int K)
{
    extern __shared__ char smem[];
    const int z = blockIdx.z;
    gemm_tile_body<2>(A, s.b[z], nullptr, s.ch[z],
                      s.mul[z], M, N, K, blockIdx.y * 128, blockIdx.x * 128, smem);
}

// ============================================================
// Tensor-core flash attention v3 (causal) — fp16.
// Block: 256 threads (8 warps); BQ=128, BKV=64, hd=128.
// Plain __launch_bounds__(256): natural regs (~170), no spills.
// smem: Q 32KB + 2 stages x 32KB = 96 KB. (Measured-best: 251.9 us.)
// ============================================================
#define FT_Q     0
#define FT_STAGE 32768
#define FS_K     0
#define FS_V     16384
#define FLASH_TC_SMEM 98304

__device__ __forceinline__ uint32_t fsw(int row, int c16) {
    return (uint32_t)(row * 256 + ((c16 ^ ((row & 7) << 1)) << 4));
}

__global__ __launch_bounds__(256) void flash_attn_tc_kernel(
    const __half* __restrict__ qh, const __half* __restrict__ kh,
    const __half* __restrict__ vh, __half* __restrict__ oh)
{
    extern __shared__ char fsm[];
    const uint32_t sb = smem_u32(fsm);
    const int tid = threadIdx.x;
    const int wid = tid >> 5;
    const int l   = tid & 31;
    const int qt = gridDim.x - 1 - blockIdx.x;   // longest-first scheduling
    const int h  = blockIdx.y;
    const int b  = blockIdx.z;
    const int q0 = qt * 128;

    const size_t gq = ((size_t)b * SEQ + q0) * DMODEL + h * HDIM;
    #pragma unroll
    for (int i = 0; i < 8; i++) {
        int idx = tid + i * 256;
        int row = idx >> 4, c16 = idx & 15;
        cp_async16(sb + FT_Q + fsw(row, c16), qh + gq + (size_t)row * DMODEL + c16 * 8);
    }
    cp_commit();

    auto issue_kv = [&](int kt, int sidx) {
        uint32_t s0 = sb + FT_STAGE + sidx * 32768;
        const size_t gkv = ((size_t)b * SEQ + kt * 64) * DMODEL + h * HDIM;
        #pragma unroll
        for (int i = 0; i < 4; i++) {
            int idx = tid + i * 256;
            int row = idx >> 4, c16 = idx & 15;
            uint32_t off = fsw(row, c16);
            size_t src = gkv + (size_t)row * DMODEL + c16 * 8;
            cp_async16(s0 + FS_K + off, kh + src);
            cp_async16(s0 + FS_V + off, vh + src);
        }
        cp_commit();
    };

    const int r  = l >> 2;
    const int cq = l & 3;
    const int a_rowoff = (l & 15);
    const int a_c16off = (l >> 4);
    const int b_rowoff = (l & 7) | ((l & 16) >> 1);
    const int b_c16off = (l >> 3) & 1;
    const int wrow0 = q0 + wid * 16;

    float m0v = -1e30f, m1v = -1e30f, l0v = 0.f, l1v = 0.f;
    float O[16][4];
    #pragma unroll
    for (int g = 0; g < 16; g++)
        #pragma unroll
        for (int t = 0; t < 4; t++) O[g][t] = 0.f;

    const int nkt = 2 * qt + 2;
    issue_kv(0, 0);

    for (int kt = 0; kt < nkt; kt++) {
        const int sidx = kt & 1;
        if (kt + 1 < nkt) issue_kv(kt + 1, sidx ^ 1);
        if (kt + 1 < nkt) cp_wait1(); else cp_wait0();
        __syncthreads();

        const int col0 = kt * 64;
        if (col0 <= wrow0 + 15) {        // warp-level causal skip
            const uint32_t s0 = sb + FT_STAGE + sidx * 32768;

            float s[8][4];
            #pragma unroll
            for (int nj = 0; nj < 8; nj++)
                #pragma unroll
                for (int t = 0; t < 4; t++) s[nj][t] = 0.f;

            #pragma unroll
            for (int j = 0; j < 8; j++) {
                int arow = wid * 16 + a_rowoff;
                uint32_t ah[4];
                ldm_x4(ah[0], ah[1], ah[2], ah[3], sb + FT_Q + fsw(arow, 2 * j + a_c16off));

                uint32_t bh[8][2];
                #pragma unroll
                for (int p = 0; p < 4; p++) {
                    int brow = p * 16 + b_rowoff;
                    uint32_t bad = s0 + FS_K + fsw(brow, 2 * j + b_c16off);
                    ldm_x4(bh[2*p][0], bh[2*p][1], bh[2*p+1][0], bh[2*p+1][1], bad);
                }
                #pragma unroll
                for (int nj = 0; nj < 8; nj++)
                    mma_f16(s[nj], ah, bh[nj][0], bh[nj][1]);
            }

            if (col0 + 63 > wrow0) {
                #pragma unroll
                for (int nj = 0; nj < 8; nj++)
                    #pragma unroll
                    for (int t = 0; t < 4; t++) {
                        int coll = col0 + nj * 8 + 2 * cq + (t & 1);
                        int rowl = wrow0 + r + ((t >> 1) << 3);
                        if (coll > rowl) s[nj][t] = -1e30f;
                    }
            }

            float mx0 = -1e30f, mx1 = -1e30f;
            #pragma unroll
            for (int nj = 0; nj < 8; nj++) {
                mx0 = fmaxf(mx0, fmaxf(s[nj][0], s[nj][1]));
                mx1 = fmaxf(mx1, fmaxf(s[nj][2], s[nj][3]));
            }
            mx0 = fmaxf(mx0, __shfl_xor_sync(0xffffffffu, mx0, 1));
            mx0 = fmaxf(mx0, __shfl_xor_sync(0xffffffffu, mx0, 2));
            mx1 = fmaxf(mx1, __shfl_xor_sync(0xffffffffu, mx1, 1));
            mx1 = fmaxf(mx1, __shfl_xor_sync(0xffffffffu, mx1, 2));

            float mn0 = fmaxf(m0v, mx0), mn1 = fmaxf(m1v, mx1);
            float al0 = __expf(m0v - mn0), al1 = __expf(m1v - mn1);
            m0v = mn0; m1v = mn1;

            #pragma unroll
            for (int g = 0; g < 16; g++) {
                O[g][0] *= al0; O[g][1] *= al0;
                O[g][2] *= al1; O[g][3] *= al1;
            }

            float rs0 = 0.f, rs1 = 0.f;
            #pragma unroll
            for (int nj = 0; nj < 8; nj++) {
                s[nj][0] = __expf(s[nj][0] - mn0);
                s[nj][1] = __expf(s[nj][1] - mn0);
                s[nj][2] = __expf(s[nj][2] - mn1);
                s[nj][3] = __expf(s[nj][3] - mn1);
                rs0 += s[nj][0] + s[nj][1];
                rs1 += s[nj][2] + s[nj][3];
            }
            rs0 += __shfl_xor_sync(0xffffffffu, rs0, 1);
            rs0 += __shfl_xor_sync(0xffffffffu, rs0, 2);
            rs1 += __shfl_xor_sync(0xffffffffu, rs1, 1);
            rs1 += __shfl_xor_sync(0xffffffffu, rs1, 2);
            l0v = l0v * al0 + rs0;
            l1v = l1v * al1 + rs1;

            #pragma unroll
            for (int j = 0; j < 4; j++) {
                uint32_t pa[4];
                pa[0] = pack_f16x2(s[2*j][0],   s[2*j][1]);
                pa[1] = pack_f16x2(s[2*j][2],   s[2*j][3]);
                pa[2] = pack_f16x2(s[2*j+1][0], s[2*j+1][1]);
                pa[3] = pack_f16x2(s[2*j+1][2], s[2*j+1][3]);
                #pragma unroll
                for (int g = 0; g < 8; g++) {
                    int vrow = j * 16 + (l & 15);
                    uint32_t vad = s0 + FS_V + fsw(vrow, 2 * g + (l >> 4));
                    uint32_t v0, v1, v2, v3;
                    ldm_x4_t(v0, v1, v2, v3, vad);
                    mma_f16(O[2*g],     pa, v0, v1);
                    mma_f16(O[2*g + 1], pa, v2, v3);
                }
            }
        }
        __syncthreads();
    }

    const float i0 = 1.0f / l0v;
    const float i1 = 1.0f / l1v;
    const size_t obase = ((size_t)b * SEQ + q0 + wid * 16 + r) * DMODEL + h * HDIM;
    #pragma unroll
    for (int g = 0; g < 16; g++) {
        int col = g * 8 + 2 * cq;
        *(uint32_t*)&oh[obase + col] = pack_f16x2(O[g][0] * i0, O[g][1] * i0);
        *(uint32_t*)&oh[obase + (size_t)8 * DMODEL + col] =
            pack_f16x2(O[g][2] * i1, O[g][3] * i1);
    }
}

// ============================================================
// launcher
// ============================================================
extern "C" void kernel_launch(void* const* d_in, const int* in_sizes, int n_in,
                              void* d_out, int out_size)
{
    const float* x  = (const float*)d_in[0];
    const float* Wq = (const float*)d_in[1];
    const float* Wk = (const float*)d_in[2];
    const float* Wv = (const float*)d_in[3];
    const float* Wp = (const float*)d_in[4];
    float* out = (float*)d_out;

    void *xh, *qh, *kh, *vh, *aoh;
    cudaGetSymbolAddress(&xh,  g_xh);
    cudaGetSymbolAddress(&qh,  g_qh);
    cudaGetSymbolAddress(&kh,  g_kh);
    cudaGetSymbolAddress(&vh,  g_vh);
    cudaGetSymbolAddress(&aoh, g_aoh);

    void *wqh, *wkh, *wvh, *wph;
    cudaGetSymbolAddress(&wqh, g_wqh);
    cudaGetSymbolAddress(&wkh, g_wkh);
    cudaGetSymbolAddress(&wvh, g_wvh);
    cudaGetSymbolAddress(&wph, g_wph);

    cudaFuncSetAttribute(flash_attn_tc_kernel,
                         cudaFuncAttributeMaxDynamicSharedMemorySize, FLASH_TC_SMEM);
    cudaFuncSetAttribute(gemm_f32out_kernel,
                         cudaFuncAttributeMaxDynamicSharedMemorySize, GEMM_SMEM);
    cudaFuncSetAttribute(gemm_qkv_kernel,
                         cudaFuncAttributeMaxDynamicSharedMemorySize, GEMM_SMEM);

    const int nx4 = (MROWS * DMODEL) / 4;
    const int nw4 = (DMODEL * DMODEL) / 4;

    {
        CvtSet sx;
        sx.src[0] = x; sx.dst[0] = (__half*)xh;
        dim3 g1((nx4 + 255) / 256, 1);
        cvt4_f16_kernel<<<g1, 256>>>(sx, nx4);

        CvtSet sw;
        sw.src[0] = Wq; sw.dst[0] = (__half*)wqh;
        sw.src[1] = Wk; sw.dst[1] = (__half*)wkh;
        sw.src[2] = Wv; sw.dst[2] = (__half*)wvh;
        sw.src[3] = Wp; sw.dst[3] = (__half*)wph;
        dim3 g4((nw4 + 255) / 256, 4);
        cvt4_f16_kernel<<<g4, 256>>>(sw, nw4);
    }

    const float scale = 0.08838834764831845f;  // 1/sqrt(128), folded into Q

    {
        QKVSet qs;
        qs.b[0] = (const __half*)wqh; qs.ch[0] = (__half*)qh; qs.mul[0] = scale;
        qs.b[1] = (const __half*)wkh; qs.ch[1] = (__half*)kh; qs.mul[1] = 1.0f;
        qs.b[2] = (const __half*)wvh; qs.ch[2] = (__half*)vh; qs.mul[2] = 1.0f;
        dim3 qg(DMODEL / 128, MROWS / 128, 3);   // (16, 32, 3)
        gemm_qkv_kernel<<<qg, 256, GEMM_SMEM>>>(
            (const __half*)xh, qs, MROWS, DMODEL, DMODEL);
    }

    dim3 fgrid(SEQ / 128, NHEAD, BATCH);     // (16, 16, 2)
    flash_attn_tc_kernel<<<fgrid, 256, FLASH_TC_SMEM>>>(
        (const __half*)qh, (const __half*)kh, (const __half*)vh, (__half*)aoh);

    dim3 ggrid(DMODEL / 128, MROWS / 128);   // (16, 32)
    gemm_f32out_kernel<<<ggrid, 256, GEMM_SMEM>>>(
        (const __half*)aoh, (const __half*)wph,
        out, MROWS, DMODEL, DMODEL);
}